// round 15
// baseline (speedup 1.0000x reference)
#include <cuda_runtime.h>
#include <cuda_fp16.h>
#include <stdint.h>

// Problem constants (fixed by the reference)
#define BATCH 1024
#define IN_SIZE 2048
#define OUT_SIZE 2048
#define EMAX 131072

#define BK 64                           // halves per K chunk (128B = SW128 row)
#define NCHUNKS (IN_SIZE / BK)          // 32
#define A_TILE_BYTES 8192               // 64 rows x 128 bytes
#define B_TILE_BYTES 16384              // 128 rows x 128 bytes
#define STAGE_BYTES (A_TILE_BYTES + B_TILE_BYTES)   // 24 KB
#define NSTAGES 3
#define SMEM_TOTAL (NSTAGES * STAGE_BYTES)          // 72 KB -> 2 CTAs/SM

// -------- device scratch (no allocations allowed) --------
// INVARIANT: g_Wh is all-zero at kernel_launch entry. It is zero-initialized
// at module load, and cleanup_kernel re-zeroes every touched slot after the
// GEMM on every call (idempotent; same edge set every call -> deterministic).
__device__ __half g_Wh[OUT_SIZE * IN_SIZE];    // 8 MB dense weights fp16 [out][in]
__device__ __half g_xh[BATCH * IN_SIZE];       // 4 MB x fp16 [batch][in]

__device__ __forceinline__ int fetch_idx(const void* p, int e, int is64) {
    if (is64) return (int)(((const long long*)p)[e]);
    return ((const int*)p)[e];
}

// per-block index-dtype detection (no cross-kernel dependency)
__device__ __forceinline__ int detect64(const void* in_idx, int E) {
    __shared__ int s_is64;
    if (threadIdx.x < 32) {
        const long long* q = (const long long*)in_idx;
        long long v = ((int)threadIdx.x < E) ? q[threadIdx.x] : 0;
        bool bad = (v < 0 || v >= IN_SIZE);
        unsigned m = __ballot_sync(0xFFFFFFFFu, bad);
        if (threadIdx.x == 0) s_is64 = (m == 0) ? 1 : 0;
    }
    __syncthreads();
    return s_is64;
}

// ---------------- helpers ----------------
__device__ __forceinline__ uint32_t smem_u32(const void* p) {
    uint32_t a;
    asm("{ .reg .u64 t; cvta.to.shared.u64 t, %1; cvt.u32.u64 %0, t; }"
        : "=r"(a) : "l"(p));
    return a;
}
#define SWZ128(off) ((off) ^ (((off) >> 3) & 0x70))
#define CP_ASYNC16(dst, src) \
    asm volatile("cp.async.cg.shared.global [%0], [%1], 16;" :: "r"(dst), "l"(src))
#define CP_COMMIT() asm volatile("cp.async.commit_group;" ::: "memory")
#define CP_WAIT1()  asm volatile("cp.async.wait_group 1;" ::: "memory")
#define LDSM4(r0, r1, r2, r3, a)                                               \
    asm volatile("ldmatrix.sync.aligned.m8n8.x4.shared.b16 {%0,%1,%2,%3}, [%4];" \
                 : "=r"(r0), "=r"(r1), "=r"(r2), "=r"(r3) : "r"(a))
#define MMA16816(c, a, b0, b1)                                                 \
    asm volatile(                                                              \
        "mma.sync.aligned.m16n8k16.row.col.f32.f16.f16.f32 "                   \
        "{%0,%1,%2,%3}, {%4,%5,%6,%7}, {%8,%9}, {%0,%1,%2,%3};"                \
        : "+f"(c[0]), "+f"(c[1]), "+f"(c[2]), "+f"(c[3])                       \
        : "r"(a[0]), "r"(a[1]), "r"(a[2]), "r"(a[3]), "r"(b0), "r"(b1))

// -------- 1. build: convert x (blocks 0..2047) + scatter W (2048..2559) -----
// W is already all-zero (invariant), so scatter needs no prior zeroing pass
// and both halves are independent -> one kernel, one launch.
__global__ void __launch_bounds__(256) build_kernel(
    const float* __restrict__ x, const void* in_idx, const void* out_idx,
    const float* __restrict__ w, int E) {
    if (blockIdx.x < 2048) {
        int t = blockIdx.x * 256 + threadIdx.x;   // [0, 524288)
        float4 v = reinterpret_cast<const float4*>(x)[t];
        __half2 h0 = __floats2half2_rn(v.x, v.y);
        __half2 h1 = __floats2half2_rn(v.z, v.w);
        reinterpret_cast<__half2*>(g_xh)[2 * t]     = h0;
        reinterpret_cast<__half2*>(g_xh)[2 * t + 1] = h1;
    } else {
        int is64 = detect64(in_idx, E);
        int e = (blockIdx.x - 2048) * 256 + threadIdx.x;
        if (e >= E) return;
        int o = fetch_idx(out_idx, e, is64);
        int i = fetch_idx(in_idx, e, is64);
        int idx = o * IN_SIZE + i;
        const __half zero = __ushort_as_half((unsigned short)0);
        __half hw = __float2half_rn(w[e]);
        __half2* p = reinterpret_cast<__half2*>(g_Wh + (idx & ~1));
        __half2 v = (idx & 1) ? __halves2half2(zero, hw)
                              : __halves2half2(hw, zero);
        atomicAdd(p, v);
    }
}

// -------- 2. GEMM: out[b][o] = sum_k xh[b][k] * Wh[o][k] --------------------
// CTA tile M64 x N128 (256 CTAs, 2 CTAs/SM co-resident), 8 warps in 2x4
// (32x32 per warp), BK=64, 3-stage cp.async pipeline, mma.m16n8k16 fp32-acc.
// One barrier per chunk (top-of-loop): stage (ch+2)%3 being filled was
// consumed at iter ch-1, and every warp passed this iter's barrier after it.
__global__ void __launch_bounds__(256, 2) gemm_kernel(float* __restrict__ out) {
    extern __shared__ char smem[];
    uint32_t sb = smem_u32(smem);
    int t = threadIdx.x;
    int wid = t >> 5;
    int lane = t & 31;
    int m0 = blockIdx.y << 6;   // batch tile origin (64 rows)
    int n0 = blockIdx.x << 7;   // out tile origin (128 cols)
    int wm = (wid & 1) << 5;    // warp m-origin (0/32)
    int wn = (wid >> 1) << 5;   // warp n-origin (0/32/64/96)

    const __half* axh = g_xh + (size_t)m0 * IN_SIZE;
    const __half* bwh = g_Wh + (size_t)n0 * IN_SIZE;

    auto load_tile = [&](int kc, int s) {
        uint32_t stage = sb + s * STAGE_BYTES;
        const __half* as = axh + kc * BK;
        const __half* bs = bwh + kc * BK;
#pragma unroll
        for (int q = t; q < 1536; q += 256) {
            if (q < 512) {
                int r = q >> 3, sg = q & 7;
                CP_ASYNC16(stage + SWZ128((r << 7) + (sg << 4)),
                           as + (size_t)r * IN_SIZE + sg * 8);
            } else {
                int q2 = q - 512;
                int r = q2 >> 3, sg = q2 & 7;
                CP_ASYNC16(stage + A_TILE_BYTES + SWZ128((r << 7) + (sg << 4)),
                           bs + (size_t)r * IN_SIZE + sg * 8);
            }
        }
        CP_COMMIT();
    };

    float c[2][4][4];
#pragma unroll
    for (int a = 0; a < 2; a++)
#pragma unroll
        for (int b = 0; b < 4; b++)
#pragma unroll
            for (int k = 0; k < 4; k++) c[a][b][k] = 0.f;

    load_tile(0, 0);
    load_tile(1, 1);

    int a_row = wm + (lane & 15);                      // + mi*16
    int a_kh = (lane >> 4) << 3;
    int b_row = wn + (lane & 7) + ((lane >> 4) << 3);  // + nj*16
    int b_kh = ((lane >> 3) & 1) << 3;

    for (int ch = 0; ch < NCHUNKS; ch++) {
        CP_WAIT1();            // chunk ch landed; ch+1 may be in flight
        __syncthreads();       // data visible + all warps done with ch-1
        if (ch + 2 < NCHUNKS) load_tile(ch + 2, (ch + 2) % NSTAGES);
        uint32_t sA = sb + (ch % NSTAGES) * STAGE_BYTES;
        uint32_t sB = sA + A_TILE_BYTES;
#pragma unroll
        for (int kk = 0; kk < BK; kk += 16) {
            uint32_t af[2][4], bf[2][4];
#pragma unroll
            for (int mi = 0; mi < 2; mi++) {
                uint32_t ad = sA + SWZ128(((a_row + (mi << 4)) << 7) +
                                          ((kk + a_kh) << 1));
                LDSM4(af[mi][0], af[mi][1], af[mi][2], af[mi][3], ad);
            }
#pragma unroll
            for (int nj = 0; nj < 2; nj++) {
                uint32_t bd = sB + SWZ128(((b_row + (nj << 4)) << 7) +
                                          ((kk + b_kh) << 1));
                LDSM4(bf[nj][0], bf[nj][1], bf[nj][2], bf[nj][3], bd);
            }
#pragma unroll
            for (int mi = 0; mi < 2; mi++)
#pragma unroll
                for (int j = 0; j < 4; j++)
                    MMA16816(c[mi][j], af[mi],
                             bf[j >> 1][(j & 1) << 1],
                             bf[j >> 1][((j & 1) << 1) + 1]);
        }
    }

    // epilogue: write fp32 accumulators straight to d_out (float2 stores)
    int rbase = m0 + wm + (lane >> 2);
    int cbase = n0 + wn + ((lane & 3) << 1);
#pragma unroll
    for (int mi = 0; mi < 2; mi++) {
#pragma unroll
        for (int j = 0; j < 4; j++) {
            int row = rbase + (mi << 4);
            int col = cbase + (j << 3);
            *reinterpret_cast<float2*>(out + (size_t)row * OUT_SIZE + col) =
                make_float2(c[mi][j][0], c[mi][j][1]);
            *reinterpret_cast<float2*>(out + (size_t)(row + 8) * OUT_SIZE + col) =
                make_float2(c[mi][j][2], c[mi][j][3]);
        }
    }
}

// -------- 3. cleanup: restore the all-zero W invariant ----------------------
// Re-zero exactly the half2 pairs the scatter touched. Idempotent (duplicate
// edges write the same 0), so races between duplicates are benign.
__global__ void __launch_bounds__(256) cleanup_kernel(const void* in_idx,
                                                      const void* out_idx,
                                                      int E) {
    int is64 = detect64(in_idx, E);
    int e = blockIdx.x * 256 + threadIdx.x;
    if (e >= E) return;
    int o = fetch_idx(out_idx, e, is64);
    int i = fetch_idx(in_idx, e, is64);
    int idx = o * IN_SIZE + i;
    reinterpret_cast<unsigned*>(g_Wh)[idx >> 1] = 0u;
}

extern "C" void kernel_launch(void* const* d_in, const int* in_sizes, int n_in,
                              void* d_out, int out_size) {
    const float* x       = (const float*)d_in[0];
    const float* weights = (const float*)d_in[1];
    const void*  in_idx  = d_in[2];
    const void*  out_idx = d_in[3];
    float* out = (float*)d_out;
    int E = in_sizes[1];
    if (E > EMAX) E = EMAX;

    cudaFuncSetAttribute(gemm_kernel,
                         cudaFuncAttributeMaxDynamicSharedMemorySize, SMEM_TOTAL);

    int sblk = (E + 255) / 256;   // scatter blocks (512 for E=131072)

    // 1. fused build: convert x + scatter edges into (already-zero) W
    build_kernel<<<2048 + sblk, 256>>>(x, in_idx, out_idx, weights, E);

    // 2. tensor-core GEMM, 256 CTAs (2 co-resident per SM)
    dim3 grid(OUT_SIZE / 128, BATCH / 64);  // 16 x 16 = 256 CTAs
    gemm_kernel<<<grid, 256, SMEM_TOTAL>>>(out);

    // 3. restore the all-zero W invariant for the next call / replay
    cleanup_kernel<<<sblk, 256>>>(in_idx, out_idx, E);
}

// round 16
// speedup vs baseline: 1.7207x; 1.7207x over previous
#include <cuda_runtime.h>
#include <cuda_fp16.h>
#include <stdint.h>

// Problem constants (fixed by the reference)
#define BATCH 1024
#define IN_SIZE 2048
#define OUT_SIZE 2048
#define EMAX 131072

#define BK 64                           // halves per K chunk (128B = SW128 row)
#define NCHUNKS (IN_SIZE / BK)          // 32
#define A_TILE_BYTES 8192               // 64 rows x 128 bytes
#define B_TILE_BYTES 16384              // 128 rows x 128 bytes
#define STAGE_BYTES (A_TILE_BYTES + B_TILE_BYTES)   // 24 KB
#define NSTAGES 3
#define SMEM_TOTAL (NSTAGES * STAGE_BYTES)          // 72 KB -> 2 CTAs/SM

// -------- device scratch (no allocations allowed) --------
__device__ __half g_Wh[OUT_SIZE * IN_SIZE];    // 8 MB dense weights fp16 [out][in]
__device__ __half g_xh[BATCH * IN_SIZE];       // 4 MB x fp16 [batch][in]

__device__ __forceinline__ int fetch_idx(const void* p, int e, int is64) {
    if (is64) return (int)(((const long long*)p)[e]);
    return ((const int*)p)[e];
}

// per-block index-dtype detection (no cross-kernel dependency)
__device__ __forceinline__ int detect64(const void* in_idx, int E) {
    __shared__ int s_is64;
    if (threadIdx.x < 32) {
        const long long* q = (const long long*)in_idx;
        long long v = ((int)threadIdx.x < E) ? q[threadIdx.x] : 0;
        bool bad = (v < 0 || v >= IN_SIZE);
        unsigned m = __ballot_sync(0xFFFFFFFFu, bad);
        if (threadIdx.x == 0) s_is64 = (m == 0) ? 1 : 0;
    }
    __syncthreads();
    return s_is64;
}

// ---------------- helpers ----------------
__device__ __forceinline__ uint32_t smem_u32(const void* p) {
    uint32_t a;
    asm("{ .reg .u64 t; cvta.to.shared.u64 t, %1; cvt.u32.u64 %0, t; }"
        : "=r"(a) : "l"(p));
    return a;
}
#define SWZ128(off) ((off) ^ (((off) >> 3) & 0x70))
#define CP_ASYNC16(dst, src) \
    asm volatile("cp.async.cg.shared.global [%0], [%1], 16;" :: "r"(dst), "l"(src))
#define CP_COMMIT() asm volatile("cp.async.commit_group;" ::: "memory")
#define CP_WAIT1()  asm volatile("cp.async.wait_group 1;" ::: "memory")
#define LDSM4(r0, r1, r2, r3, a)                                               \
    asm volatile("ldmatrix.sync.aligned.m8n8.x4.shared.b16 {%0,%1,%2,%3}, [%4];" \
                 : "=r"(r0), "=r"(r1), "=r"(r2), "=r"(r3) : "r"(a))
#define MMA16816(c, a, b0, b1)                                                 \
    asm volatile(                                                              \
        "mma.sync.aligned.m16n8k16.row.col.f32.f16.f16.f32 "                   \
        "{%0,%1,%2,%3}, {%4,%5,%6,%7}, {%8,%9}, {%0,%1,%2,%3};"                \
        : "+f"(c[0]), "+f"(c[1]), "+f"(c[2]), "+f"(c[3])                       \
        : "r"(a[0]), "r"(a[1]), "r"(a[2]), "r"(a[3]), "r"(b0), "r"(b1))

// -------- 1. build: scatter W (blocks 0..sblk-1) + convert x (rest) ---------
// Runs AFTER the cudaMemsetAsync node that zeroes g_Wh (stream-ordered), so
// scatter lands on zeroed W. Scatter blocks are scheduled FIRST so they run
// in wave 1 concurrently with the convert blocks.
__global__ void __launch_bounds__(256) build_kernel(
    const float* __restrict__ x, const void* in_idx, const void* out_idx,
    const float* __restrict__ w, int E, int sblk) {
    if ((int)blockIdx.x < sblk) {
        int is64 = detect64(in_idx, E);
        int e = blockIdx.x * 256 + threadIdx.x;
        if (e >= E) return;
        int o = fetch_idx(out_idx, e, is64);
        int i = fetch_idx(in_idx, e, is64);
        int idx = o * IN_SIZE + i;
        const __half zero = __ushort_as_half((unsigned short)0);
        __half hw = __float2half_rn(w[e]);
        __half2* p = reinterpret_cast<__half2*>(g_Wh + (idx & ~1));
        __half2 v = (idx & 1) ? __halves2half2(zero, hw)
                              : __halves2half2(hw, zero);
        atomicAdd(p, v);
    } else {
        int t = (blockIdx.x - sblk) * 256 + threadIdx.x;   // [0, 524288)
        float4 v = reinterpret_cast<const float4*>(x)[t];
        __half2 h0 = __floats2half2_rn(v.x, v.y);
        __half2 h1 = __floats2half2_rn(v.z, v.w);
        reinterpret_cast<__half2*>(g_xh)[2 * t]     = h0;
        reinterpret_cast<__half2*>(g_xh)[2 * t + 1] = h1;
    }
}

// -------- 2. GEMM: out[b][o] = sum_k xh[b][k] * Wh[o][k] --------------------
// CTA tile M64 x N128 (256 CTAs, 2 CTAs/SM co-resident), 8 warps in 2x4
// (32x32 per warp), BK=64, 3-stage cp.async pipeline, mma.m16n8k16 fp32-acc.
// Two barriers per chunk — the lockstep is load-bearing (R15 regression).
__global__ void __launch_bounds__(256, 2) gemm_kernel(float* __restrict__ out) {
    extern __shared__ char smem[];
    uint32_t sb = smem_u32(smem);
    int t = threadIdx.x;
    int wid = t >> 5;
    int lane = t & 31;
    int m0 = blockIdx.y << 6;   // batch tile origin (64 rows)
    int n0 = blockIdx.x << 7;   // out tile origin (128 cols)
    int wm = (wid & 1) << 5;    // warp m-origin (0/32)
    int wn = (wid >> 1) << 5;   // warp n-origin (0/32/64/96)

    const __half* axh = g_xh + (size_t)m0 * IN_SIZE;
    const __half* bwh = g_Wh + (size_t)n0 * IN_SIZE;

    auto load_tile = [&](int kc, int s) {
        uint32_t stage = sb + s * STAGE_BYTES;
        const __half* as = axh + kc * BK;
        const __half* bs = bwh + kc * BK;
#pragma unroll
        for (int q = t; q < 1536; q += 256) {
            if (q < 512) {
                int r = q >> 3, sg = q & 7;
                CP_ASYNC16(stage + SWZ128((r << 7) + (sg << 4)),
                           as + (size_t)r * IN_SIZE + sg * 8);
            } else {
                int q2 = q - 512;
                int r = q2 >> 3, sg = q2 & 7;
                CP_ASYNC16(stage + A_TILE_BYTES + SWZ128((r << 7) + (sg << 4)),
                           bs + (size_t)r * IN_SIZE + sg * 8);
            }
        }
        CP_COMMIT();
    };

    float c[2][4][4];
#pragma unroll
    for (int a = 0; a < 2; a++)
#pragma unroll
        for (int b = 0; b < 4; b++)
#pragma unroll
            for (int k = 0; k < 4; k++) c[a][b][k] = 0.f;

    load_tile(0, 0);
    load_tile(1, 1);

    int a_row = wm + (lane & 15);                      // + mi*16
    int a_kh = (lane >> 4) << 3;
    int b_row = wn + (lane & 7) + ((lane >> 4) << 3);  // + nj*16
    int b_kh = ((lane >> 3) & 1) << 3;

    for (int ch = 0; ch < NCHUNKS; ch++) {
        CP_WAIT1();            // chunk ch landed; ch+1 may be in flight
        __syncthreads();
        if (ch + 2 < NCHUNKS) load_tile(ch + 2, (ch + 2) % NSTAGES);
        uint32_t sA = sb + (ch % NSTAGES) * STAGE_BYTES;
        uint32_t sB = sA + A_TILE_BYTES;
#pragma unroll
        for (int kk = 0; kk < BK; kk += 16) {
            uint32_t af[2][4], bf[2][4];
#pragma unroll
            for (int mi = 0; mi < 2; mi++) {
                uint32_t ad = sA + SWZ128(((a_row + (mi << 4)) << 7) +
                                          ((kk + a_kh) << 1));
                LDSM4(af[mi][0], af[mi][1], af[mi][2], af[mi][3], ad);
            }
#pragma unroll
            for (int nj = 0; nj < 2; nj++) {
                uint32_t bd = sB + SWZ128(((b_row + (nj << 4)) << 7) +
                                          ((kk + b_kh) << 1));
                LDSM4(bf[nj][0], bf[nj][1], bf[nj][2], bf[nj][3], bd);
            }
#pragma unroll
            for (int mi = 0; mi < 2; mi++)
#pragma unroll
                for (int j = 0; j < 4; j++)
                    MMA16816(c[mi][j], af[mi],
                             bf[j >> 1][(j & 1) << 1],
                             bf[j >> 1][((j & 1) << 1) + 1]);
        }
        __syncthreads();
    }

    // epilogue: write fp32 accumulators straight to d_out (float2 stores)
    int rbase = m0 + wm + (lane >> 2);
    int cbase = n0 + wn + ((lane & 3) << 1);
#pragma unroll
    for (int mi = 0; mi < 2; mi++) {
#pragma unroll
        for (int j = 0; j < 4; j++) {
            int row = rbase + (mi << 4);
            int col = cbase + (j << 3);
            *reinterpret_cast<float2*>(out + (size_t)row * OUT_SIZE + col) =
                make_float2(c[mi][j][0], c[mi][j][1]);
            *reinterpret_cast<float2*>(out + (size_t)(row + 8) * OUT_SIZE + col) =
                make_float2(c[mi][j][2], c[mi][j][3]);
        }
    }
}

extern "C" void kernel_launch(void* const* d_in, const int* in_sizes, int n_in,
                              void* d_out, int out_size) {
    const float* x       = (const float*)d_in[0];
    const float* weights = (const float*)d_in[1];
    const void*  in_idx  = d_in[2];
    const void*  out_idx = d_in[3];
    float* out = (float*)d_out;
    int E = in_sizes[1];
    if (E > EMAX) E = EMAX;

    cudaFuncSetAttribute(gemm_kernel,
                         cudaFuncAttributeMaxDynamicSharedMemorySize, SMEM_TOTAL);

    // 1. zero W via a memset node (graph-capturable, near-peak BW)
    void* wptr = nullptr;
    cudaGetSymbolAddress(&wptr, g_Wh);
    cudaMemsetAsync(wptr, 0, (size_t)OUT_SIZE * IN_SIZE * sizeof(__half), 0);

    // 2. fused build: scatter edges (first wave) + convert x
    int sblk = (E + 255) / 256;   // 512 for E=131072
    build_kernel<<<sblk + 2048, 256>>>(x, in_idx, out_idx, weights, E, sblk);

    // 3. tensor-core GEMM, 256 CTAs (2 co-resident per SM)
    dim3 grid(OUT_SIZE / 128, BATCH / 64);  // 16 x 16 = 256 CTAs
    gemm_kernel<<<grid, 256, SMEM_TOTAL>>>(out);
}

// round 17
// speedup vs baseline: 1.7325x; 1.0069x over previous
#include <cuda_runtime.h>
#include <cuda_fp16.h>
#include <stdint.h>

// Problem constants (fixed by the reference)
#define BATCH 1024
#define IN_SIZE 2048
#define OUT_SIZE 2048
#define EMAX 131072

#define BK 64                           // halves per K chunk (128B = SW128 row)
#define NCHUNKS (IN_SIZE / BK)          // 32
#define A_TILE_BYTES 8192               // 64 rows x 128 bytes
#define B_TILE_BYTES 16384              // 128 rows x 128 bytes
#define STAGE_BYTES (A_TILE_BYTES + B_TILE_BYTES)   // 24 KB
#define NSTAGES 3
#define SMEM_TOTAL (NSTAGES * STAGE_BYTES)          // 72 KB -> 2 CTAs/SM

// -------- device scratch (no allocations allowed) --------
__device__ __half g_Wh[OUT_SIZE * IN_SIZE];    // 8 MB dense weights fp16 [out][in]
__device__ __half g_xh[BATCH * IN_SIZE];       // 4 MB x fp16 [batch][in]

__device__ __forceinline__ int fetch_idx(const void* p, int e, int is64) {
    if (is64) return (int)(((const long long*)p)[e]);
    return ((const int*)p)[e];
}

// per-block index-dtype detection (no cross-kernel dependency)
__device__ __forceinline__ int detect64(const void* in_idx, int E) {
    __shared__ int s_is64;
    if (threadIdx.x < 32) {
        const long long* q = (const long long*)in_idx;
        long long v = ((int)threadIdx.x < E) ? q[threadIdx.x] : 0;
        bool bad = (v < 0 || v >= IN_SIZE);
        unsigned m = __ballot_sync(0xFFFFFFFFu, bad);
        if (threadIdx.x == 0) s_is64 = (m == 0) ? 1 : 0;
    }
    __syncthreads();
    return s_is64;
}

// ---------------- helpers ----------------
__device__ __forceinline__ uint32_t smem_u32(const void* p) {
    uint32_t a;
    asm("{ .reg .u64 t; cvta.to.shared.u64 t, %1; cvt.u32.u64 %0, t; }"
        : "=r"(a) : "l"(p));
    return a;
}
#define SWZ128(off) ((off) ^ (((off) >> 3) & 0x70))
#define CP_ASYNC16(dst, src) \
    asm volatile("cp.async.cg.shared.global [%0], [%1], 16;" :: "r"(dst), "l"(src))
#define CP_COMMIT() asm volatile("cp.async.commit_group;" ::: "memory")
#define CP_WAIT1()  asm volatile("cp.async.wait_group 1;" ::: "memory")
#define LDSM4(r0, r1, r2, r3, a)                                               \
    asm volatile("ldmatrix.sync.aligned.m8n8.x4.shared.b16 {%0,%1,%2,%3}, [%4];" \
                 : "=r"(r0), "=r"(r1), "=r"(r2), "=r"(r3) : "r"(a))
#define MMA16816(c, a, b0, b1)                                                 \
    asm volatile(                                                              \
        "mma.sync.aligned.m16n8k16.row.col.f32.f16.f16.f32 "                   \
        "{%0,%1,%2,%3}, {%4,%5,%6,%7}, {%8,%9}, {%0,%1,%2,%3};"                \
        : "+f"(c[0]), "+f"(c[1]), "+f"(c[2]), "+f"(c[3])                       \
        : "r"(a[0]), "r"(a[1]), "r"(a[2]), "r"(a[3]), "r"(b0), "r"(b1))

// -------- 1. build: scatter W (blocks 0..sblk-1) + convert x (rest) ---------
// Runs AFTER the cudaMemsetAsync node that zeroes g_Wh (stream-ordered).
__global__ void __launch_bounds__(256) build_kernel(
    const float* __restrict__ x, const void* in_idx, const void* out_idx,
    const float* __restrict__ w, int E, int sblk) {
    if ((int)blockIdx.x < sblk) {
        int is64 = detect64(in_idx, E);
        int e = blockIdx.x * 256 + threadIdx.x;
        if (e >= E) return;
        int o = fetch_idx(out_idx, e, is64);
        int i = fetch_idx(in_idx, e, is64);
        int idx = o * IN_SIZE + i;
        const __half zero = __ushort_as_half((unsigned short)0);
        __half hw = __float2half_rn(w[e]);
        __half2* p = reinterpret_cast<__half2*>(g_Wh + (idx & ~1));
        __half2 v = (idx & 1) ? __halves2half2(zero, hw)
                              : __halves2half2(hw, zero);
        atomicAdd(p, v);
    } else {
        int t = (blockIdx.x - sblk) * 256 + threadIdx.x;   // [0, 524288)
        float4 v = reinterpret_cast<const float4*>(x)[t];
        __half2 h0 = __floats2half2_rn(v.x, v.y);
        __half2 h1 = __floats2half2_rn(v.z, v.w);
        reinterpret_cast<__half2*>(g_xh)[2 * t]     = h0;
        reinterpret_cast<__half2*>(g_xh)[2 * t + 1] = h1;
    }
}

// -------- 2. GEMM: out[b][o] = sum_k xh[b][k] * Wh[o][k] --------------------
// CTA tile M64 x N128 (256 CTAs, 2 CTAs/SM), 8 warps 2x4 (32x32 per warp),
// BK=64, 3-stage cp.async pipeline, mma.m16n8k16 fp32-acc.
// NEW: register double-buffered fragments — LDSM for kk-step p+1 overlaps
// the MMAs of step p, breaking the LDSM->MMA serialization (tensor was 45.6%).
__global__ void __launch_bounds__(256, 2) gemm_kernel(float* __restrict__ out) {
    extern __shared__ char smem[];
    uint32_t sb = smem_u32(smem);
    int t = threadIdx.x;
    int wid = t >> 5;
    int lane = t & 31;
    int m0 = blockIdx.y << 6;   // batch tile origin (64 rows)
    int n0 = blockIdx.x << 7;   // out tile origin (128 cols)
    int wm = (wid & 1) << 5;    // warp m-origin (0/32)
    int wn = (wid >> 1) << 5;   // warp n-origin (0/32/64/96)

    const __half* axh = g_xh + (size_t)m0 * IN_SIZE;
    const __half* bwh = g_Wh + (size_t)n0 * IN_SIZE;

    auto load_tile = [&](int kc, int s) {
        uint32_t stage = sb + s * STAGE_BYTES;
        const __half* as = axh + kc * BK;
        const __half* bs = bwh + kc * BK;
#pragma unroll
        for (int q = t; q < 1536; q += 256) {
            if (q < 512) {
                int r = q >> 3, sg = q & 7;
                CP_ASYNC16(stage + SWZ128((r << 7) + (sg << 4)),
                           as + (size_t)r * IN_SIZE + sg * 8);
            } else {
                int q2 = q - 512;
                int r = q2 >> 3, sg = q2 & 7;
                CP_ASYNC16(stage + A_TILE_BYTES + SWZ128((r << 7) + (sg << 4)),
                           bs + (size_t)r * IN_SIZE + sg * 8);
            }
        }
        CP_COMMIT();
    };

    float c[2][4][4];
#pragma unroll
    for (int a = 0; a < 2; a++)
#pragma unroll
        for (int b = 0; b < 4; b++)
#pragma unroll
            for (int k = 0; k < 4; k++) c[a][b][k] = 0.f;

    load_tile(0, 0);
    load_tile(1, 1);

    int a_row = wm + (lane & 15);                      // + mi*16
    int a_kh = (lane >> 4) << 3;
    int b_row = wn + (lane & 7) + ((lane >> 4) << 3);  // + nj*16
    int b_kh = ((lane >> 3) & 1) << 3;

    // fragment double buffers
    uint32_t af[2][2][4], bf[2][2][4];

    auto ldsm_step = [&](uint32_t sA, uint32_t sB, int kk, int buf) {
#pragma unroll
        for (int mi = 0; mi < 2; mi++) {
            uint32_t ad = sA + SWZ128(((a_row + (mi << 4)) << 7) +
                                      ((kk + a_kh) << 1));
            LDSM4(af[buf][mi][0], af[buf][mi][1], af[buf][mi][2],
                  af[buf][mi][3], ad);
        }
#pragma unroll
        for (int nj = 0; nj < 2; nj++) {
            uint32_t bd = sB + SWZ128(((b_row + (nj << 4)) << 7) +
                                      ((kk + b_kh) << 1));
            LDSM4(bf[buf][nj][0], bf[buf][nj][1], bf[buf][nj][2],
                  bf[buf][nj][3], bd);
        }
    };

    auto mma_step = [&](int buf) {
#pragma unroll
        for (int mi = 0; mi < 2; mi++)
#pragma unroll
            for (int j = 0; j < 4; j++)
                MMA16816(c[mi][j], af[buf][mi],
                         bf[buf][j >> 1][(j & 1) << 1],
                         bf[buf][j >> 1][((j & 1) << 1) + 1]);
    };

    for (int ch = 0; ch < NCHUNKS; ch++) {
        CP_WAIT1();            // chunk ch landed; ch+1 may be in flight
        __syncthreads();
        if (ch + 2 < NCHUNKS) load_tile(ch + 2, (ch + 2) % NSTAGES);
        uint32_t sA = sb + (ch % NSTAGES) * STAGE_BYTES;
        uint32_t sB = sA + A_TILE_BYTES;

        ldsm_step(sA, sB, 0, 0);
#pragma unroll
        for (int kk = 0; kk < 3; kk++) {
            ldsm_step(sA, sB, (kk + 1) << 4, (kk + 1) & 1);  // prefetch next
            mma_step(kk & 1);                                 // compute current
        }
        mma_step(1);                                          // kk=3 (buf 1)
        __syncthreads();
    }

    // epilogue: write fp32 accumulators straight to d_out (float2 stores)
    int rbase = m0 + wm + (lane >> 2);
    int cbase = n0 + wn + ((lane & 3) << 1);
#pragma unroll
    for (int mi = 0; mi < 2; mi++) {
#pragma unroll
        for (int j = 0; j < 4; j++) {
            int row = rbase + (mi << 4);
            int col = cbase + (j << 3);
            *reinterpret_cast<float2*>(out + (size_t)row * OUT_SIZE + col) =
                make_float2(c[mi][j][0], c[mi][j][1]);
            *reinterpret_cast<float2*>(out + (size_t)(row + 8) * OUT_SIZE + col) =
                make_float2(c[mi][j][2], c[mi][j][3]);
        }
    }
}

extern "C" void kernel_launch(void* const* d_in, const int* in_sizes, int n_in,
                              void* d_out, int out_size) {
    const float* x       = (const float*)d_in[0];
    const float* weights = (const float*)d_in[1];
    const void*  in_idx  = d_in[2];
    const void*  out_idx = d_in[3];
    float* out = (float*)d_out;
    int E = in_sizes[1];
    if (E > EMAX) E = EMAX;

    cudaFuncSetAttribute(gemm_kernel,
                         cudaFuncAttributeMaxDynamicSharedMemorySize, SMEM_TOTAL);

    // 1. zero W via a memset node (graph-capturable, near-peak BW)
    void* wptr = nullptr;
    cudaGetSymbolAddress(&wptr, g_Wh);
    cudaMemsetAsync(wptr, 0, (size_t)OUT_SIZE * IN_SIZE * sizeof(__half), 0);

    // 2. fused build: scatter edges (first wave) + convert x
    int sblk = (E + 255) / 256;   // 512 for E=131072
    build_kernel<<<sblk + 2048, 256>>>(x, in_idx, out_idx, weights, E, sblk);

    // 3. tensor-core GEMM, 256 CTAs (2 co-resident per SM)
    dim3 grid(OUT_SIZE / 128, BATCH / 64);  // 16 x 16 = 256 CTAs
    gemm_kernel<<<grid, 256, SMEM_TOTAL>>>(out);
}